// round 4
// baseline (speedup 1.0000x reference)
#include <cuda_runtime.h>
#include <cstdint>

// Problem dims
#define H_   8
#define IN_  512
#define SEQ_ 1024
#define MID_ 2048

constexpr int BM = 128, BN = 128, BK = 16;

// ---------------- scratch (device globals; no allocation allowed) ----------------
__device__ float g_qkv [3 * IN_ * SEQ_];          //  6 MB
__device__ float g_hbuf[H_ * 3 * IN_ * MID_];     // 96 MB
__device__ float g_sq  [H_ * 3 * IN_ * SEQ_];     // 48 MB
__device__ float g_bmat[H_ * SEQ_ * SEQ_];        // 32 MB
__device__ float g_att [H_ * IN_ * SEQ_];         // 16 MB
__device__ float g_z1  [MID_ * SEQ_];             //  8 MB
__device__ float g_mout[IN_ * SEQ_];
__device__ float g_x1  [IN_ * SEQ_];
__device__ float g_x2  [IN_ * SEQ_];
__device__ float g_t   [MID_ * SEQ_];             //  8 MB

// ---------------- tf32 helpers ----------------
__device__ __forceinline__ uint32_t f2tf32(float x) {
    uint32_t y;
    asm("cvt.rna.tf32.f32 %0, %1;" : "=r"(y) : "f"(x));
    return y;
}

__device__ __forceinline__ void mma_tf32(float c[4], const uint32_t a[4], const uint32_t b[2]) {
    asm volatile(
        "mma.sync.aligned.m16n8k8.row.col.f32.tf32.tf32.f32 "
        "{%0,%1,%2,%3}, {%4,%5,%6,%7}, {%8,%9}, {%0,%1,%2,%3};\n"
        : "+f"(c[0]), "+f"(c[1]), "+f"(c[2]), "+f"(c[3])
        : "r"(a[0]), "r"(a[1]), "r"(a[2]), "r"(a[3]), "r"(b[0]), "r"(b[1]));
}

// ---------------- generic batched GEMM: C = act( op(A) * op(B) [+ Res] ) ----------------
// A: !TA -> (M,K) row-major ; TA -> stored (K,M)
// B: !TB -> (K,N) row-major ; TB -> stored (N,K)
// C: (M,N) row-major. RA/RB: relu applied to A/B elements on load.
// RO: relu on output. RES: C += Res (Res same layout as C, no batch stride needed here).
// 3xTF32 split precision: fp32-quality results from tf32 tensor cores.
template<bool TA, bool TB, bool RA, bool RB, bool RO, bool RES>
__global__ void __launch_bounds__(256)
gemm_tf32(const float* __restrict__ A, const float* __restrict__ B,
          float* __restrict__ C, const float* __restrict__ Res,
          int M, int N, int K, long long sA, long long sB, long long sC)
{
    A += (long long)blockIdx.z * sA;
    B += (long long)blockIdx.z * sB;
    C += (long long)blockIdx.z * sC;

    const int bm = blockIdx.y * BM;
    const int bn = blockIdx.x * BN;

    __shared__ uint32_t AsHi[BK][BM + 1];
    __shared__ uint32_t AsLo[BK][BM + 1];
    __shared__ uint32_t BsHi[BK][BN + 1];
    __shared__ uint32_t BsLo[BK][BN + 1];

    const int tid  = threadIdx.x;
    const int lane = tid & 31;
    const int warp = tid >> 5;
    const int wm = (warp & 1) * 64;   // 2 warps along M
    const int wn = (warp >> 1) * 32;  // 4 warps along N
    const int ar = lane >> 2;         // mma group id
    const int ac = lane & 3;          // mma thread-in-group

    float acc[4][4][4];
#pragma unroll
    for (int i = 0; i < 4; ++i)
#pragma unroll
        for (int j = 0; j < 4; ++j)
#pragma unroll
            for (int r = 0; r < 4; ++r) acc[i][j][r] = 0.f;

    for (int k0 = 0; k0 < K; k0 += BK) {
        // ---- stage A tile (128 x 16) ----
#pragma unroll
        for (int it = 0; it < (BM * BK) / 256; ++it) {
            int idx = tid + it * 256;
            int mm, kk;
            long long gidx;
            if (!TA) { mm = idx >> 4;  kk = idx & 15;  gidx = (long long)(bm + mm) * K + (k0 + kk); }
            else     { kk = idx >> 7;  mm = idx & 127; gidx = (long long)(k0 + kk) * M + (bm + mm); }
            float v = A[gidx];
            if (RA) v = fmaxf(v, 0.f);
            uint32_t hi = f2tf32(v);
            AsHi[kk][mm] = hi;
            AsLo[kk][mm] = f2tf32(v - __uint_as_float(hi));
        }
        // ---- stage B tile (16 x 128) ----
#pragma unroll
        for (int it = 0; it < (BN * BK) / 256; ++it) {
            int idx = tid + it * 256;
            int nn, kk;
            long long gidx;
            if (!TB) { kk = idx >> 7;  nn = idx & 127; gidx = (long long)(k0 + kk) * N + (bn + nn); }
            else     { nn = idx >> 4;  kk = idx & 15;  gidx = (long long)(bn + nn) * K + (k0 + kk); }
            float v = B[gidx];
            if (RB) v = fmaxf(v, 0.f);
            uint32_t hi = f2tf32(v);
            BsHi[kk][nn] = hi;
            BsLo[kk][nn] = f2tf32(v - __uint_as_float(hi));
        }
        __syncthreads();

#pragma unroll
        for (int kk = 0; kk < BK; kk += 8) {
            uint32_t a[4][4], a2[4][4], b[4][2];
            // hi(A)
#pragma unroll
            for (int i = 0; i < 4; ++i) {
                int m0 = wm + i * 16 + ar;
                a[i][0] = AsHi[kk + ac][m0];
                a[i][1] = AsHi[kk + ac][m0 + 8];
                a[i][2] = AsHi[kk + ac + 4][m0];
                a[i][3] = AsHi[kk + ac + 4][m0 + 8];
            }
            // hi(B)
#pragma unroll
            for (int j = 0; j < 4; ++j) {
                int n0 = wn + j * 8 + ar;
                b[j][0] = BsHi[kk + ac][n0];
                b[j][1] = BsHi[kk + ac + 4][n0];
            }
            // hi*hi
#pragma unroll
            for (int i = 0; i < 4; ++i)
#pragma unroll
                for (int j = 0; j < 4; ++j) mma_tf32(acc[i][j], a[i], b[j]);
            // lo(A) * hi(B)
#pragma unroll
            for (int i = 0; i < 4; ++i) {
                int m0 = wm + i * 16 + ar;
                a2[i][0] = AsLo[kk + ac][m0];
                a2[i][1] = AsLo[kk + ac][m0 + 8];
                a2[i][2] = AsLo[kk + ac + 4][m0];
                a2[i][3] = AsLo[kk + ac + 4][m0 + 8];
            }
#pragma unroll
            for (int i = 0; i < 4; ++i)
#pragma unroll
                for (int j = 0; j < 4; ++j) mma_tf32(acc[i][j], a2[i], b[j]);
            // hi(A) * lo(B)
#pragma unroll
            for (int j = 0; j < 4; ++j) {
                int n0 = wn + j * 8 + ar;
                b[j][0] = BsLo[kk + ac][n0];
                b[j][1] = BsLo[kk + ac + 4][n0];
            }
#pragma unroll
            for (int i = 0; i < 4; ++i)
#pragma unroll
                for (int j = 0; j < 4; ++j) mma_tf32(acc[i][j], a[i], b[j]);
        }
        __syncthreads();
    }

    // ---- epilogue ----
#pragma unroll
    for (int i = 0; i < 4; ++i) {
        int m0 = bm + wm + i * 16 + ar;
#pragma unroll
        for (int j = 0; j < 4; ++j) {
            int n0 = bn + wn + j * 8 + ac * 2;
            long long o0 = (long long)m0 * N + n0;
            long long o1 = o0 + 8LL * N;
            float v0 = acc[i][j][0], v1 = acc[i][j][1];
            float v2 = acc[i][j][2], v3 = acc[i][j][3];
            if (RES) {
                v0 += Res[o0]; v1 += Res[o0 + 1];
                v2 += Res[o1]; v3 += Res[o1 + 1];
            }
            if (RO) {
                v0 = fmaxf(v0, 0.f); v1 = fmaxf(v1, 0.f);
                v2 = fmaxf(v2, 0.f); v3 = fmaxf(v3, 0.f);
            }
            C[o0] = v0; C[o0 + 1] = v1;
            C[o1] = v2; C[o1 + 1] = v3;
        }
    }
}

// ---------------- fused residual add + layernorm over last axis (1024) ----------------
__global__ void add_ln_kernel(const float* __restrict__ a, const float* __restrict__ b,
                              const float* __restrict__ w, const float* __restrict__ bias,
                              float* __restrict__ out)
{
    const int row = blockIdx.x;
    const int tid = threadIdx.x;
    const long long base = (long long)row * SEQ_;
    float v[4];
    float s = 0.f, ss = 0.f;
#pragma unroll
    for (int i = 0; i < 4; ++i) {
        int col = tid + i * 256;
        float t = a[base + col] + b[base + col];
        v[i] = t; s += t; ss += t * t;
    }
#pragma unroll
    for (int o = 16; o > 0; o >>= 1) {
        s  += __shfl_xor_sync(0xffffffffu, s,  o);
        ss += __shfl_xor_sync(0xffffffffu, ss, o);
    }
    __shared__ float rs[8], rss[8];
    if ((tid & 31) == 0) { rs[tid >> 5] = s; rss[tid >> 5] = ss; }
    __syncthreads();
    s = 0.f; ss = 0.f;
#pragma unroll
    for (int i = 0; i < 8; ++i) { s += rs[i]; ss += rss[i]; }
    const float mu  = s  * (1.0f / SEQ_);
    const float var = ss * (1.0f / SEQ_) - mu * mu;
    const float inv = rsqrtf(var + 1e-6f);
#pragma unroll
    for (int i = 0; i < 4; ++i) {
        int col = tid + i * 256;
        out[base + col] = (v[i] - mu) * inv * w[col] + bias[col];
    }
}

// ---------------- host orchestration ----------------
static void launch_mha(const float* x, const float* wqkv, const float* W1, const float* W2,
                       const float* cW1, const float* cW2,
                       float* qkv, float* hbuf, float* sq, float* bmat, float* att,
                       float* z1, float* mout)
{
    // 1. qkv[c] = w_qkv[c] @ x                     (512,1024,K=512) x3
    gemm_tf32<false,false,false,false,false,false><<<dim3(SEQ_/BN, IN_/BM, 3), 256>>>(
        wqkv, x, qkv, nullptr, IN_, SEQ_, IN_,
        (long long)IN_*IN_, 0, (long long)IN_*SEQ_);
    // 2. h[h,c] = relu( relu(qkv[c]) @ W1[h,c]^T ) (512,2048,K=1024) x24
    for (int c = 0; c < 3; ++c)
        gemm_tf32<false,true,true,false,true,false><<<dim3(MID_/BN, IN_/BM, H_), 256>>>(
            qkv + (long long)c*IN_*SEQ_, W1 + (long long)c*MID_*SEQ_,
            hbuf + (long long)c*IN_*MID_, nullptr,
            IN_, MID_, SEQ_,
            0, (long long)3*MID_*SEQ_, (long long)3*IN_*MID_);
    // 3. sq[h,c] = h[h,c] @ W2[h,c]^T              (512,1024,K=2048) x24
    for (int c = 0; c < 3; ++c)
        gemm_tf32<false,true,false,false,false,false><<<dim3(SEQ_/BN, IN_/BM, H_), 256>>>(
            hbuf + (long long)c*IN_*MID_, W2 + (long long)c*SEQ_*MID_,
            sq + (long long)c*IN_*SEQ_, nullptr,
            IN_, SEQ_, MID_,
            (long long)3*IN_*MID_, (long long)3*SEQ_*MID_, (long long)3*IN_*SEQ_);
    // 4. b[h] = k[h]^T @ q[h]                      (1024,1024,K=512) x8  (TN)
    gemm_tf32<true,false,false,false,false,false><<<dim3(SEQ_/BN, SEQ_/BM, H_), 256>>>(
        sq + (long long)IN_*SEQ_, sq, bmat, nullptr,
        SEQ_, SEQ_, IN_,
        (long long)3*IN_*SEQ_, (long long)3*IN_*SEQ_, (long long)SEQ_*SEQ_);
    // 5. att[h] = v[h] @ b[h]                      (512,1024,K=1024) x8
    gemm_tf32<false,false,false,false,false,false><<<dim3(SEQ_/BN, IN_/BM, H_), 256>>>(
        sq + (long long)2*IN_*SEQ_, bmat, att, nullptr,
        IN_, SEQ_, SEQ_,
        (long long)3*IN_*SEQ_, (long long)SEQ_*SEQ_, (long long)IN_*SEQ_);
    // 6. z1t = relu( cW1 @ relu(att_flat) )        (2048,1024,K=4096)
    gemm_tf32<false,false,false,true,true,false><<<dim3(SEQ_/BN, MID_/BM, 1), 256>>>(
        cW1, att, z1, nullptr, MID_, SEQ_, H_*IN_, 0, 0, 0);
    // 7. mout = cW2 @ relu(z1t)                    (512,1024,K=2048)
    gemm_tf32<false,false,false,true,false,false><<<dim3(SEQ_/BN, IN_/BM, 1), 256>>>(
        cW2, z1, mout, nullptr, IN_, SEQ_, MID_, 0, 0, 0);
}

static void launch_ffn(const float* x2, const float* Wa, const float* Wb,
                       float* t, float* out)
{
    // t = relu( Wa @ relu(x2) )                    (2048,1024,K=512)
    gemm_tf32<false,false,false,true,true,false><<<dim3(SEQ_/BN, MID_/BM, 1), 256>>>(
        Wa, x2, t, nullptr, MID_, SEQ_, IN_, 0, 0, 0);
    // out = Wb @ relu(t) + x2                      (512,1024,K=2048)
    gemm_tf32<false,false,false,true,false,true><<<dim3(SEQ_/BN, IN_/BM, 1), 256>>>(
        Wb, t, out, x2, IN_, SEQ_, MID_, 0, 0, 0);
}

extern "C" void kernel_launch(void* const* d_in, const int* in_sizes, int n_in,
                              void* d_out, int out_size)
{
    (void)in_sizes; (void)n_in; (void)out_size;

    const float* inp     = (const float*)d_in[0];
    const float* w_qkv_1 = (const float*)d_in[1];
    const float* w_qkv_2 = (const float*)d_in[2];
    const float* mh1_W1  = (const float*)d_in[3];
    const float* mh1_W2  = (const float*)d_in[4];
    const float* mh2_W1  = (const float*)d_in[5];
    const float* mh2_W2  = (const float*)d_in[6];
    const float* c1_W1   = (const float*)d_in[7];
    const float* c1_W2   = (const float*)d_in[8];
    const float* c2_W1   = (const float*)d_in[9];
    const float* c2_W2   = (const float*)d_in[10];
    const float* l1_W1   = (const float*)d_in[11];
    const float* l1_W2   = (const float*)d_in[12];
    const float* l2_W1   = (const float*)d_in[13];
    const float* l2_W2   = (const float*)d_in[14];
    const float* norm_w  = (const float*)d_in[15];
    const float* norm_b  = (const float*)d_in[16];
    float* out = (float*)d_out;

    float *qkv, *hbuf, *sq, *bmat, *att, *z1, *mout, *x1, *x2, *t;
    cudaGetSymbolAddress((void**)&qkv,  g_qkv);
    cudaGetSymbolAddress((void**)&hbuf, g_hbuf);
    cudaGetSymbolAddress((void**)&sq,   g_sq);
    cudaGetSymbolAddress((void**)&bmat, g_bmat);
    cudaGetSymbolAddress((void**)&att,  g_att);
    cudaGetSymbolAddress((void**)&z1,   g_z1);
    cudaGetSymbolAddress((void**)&mout, g_mout);
    cudaGetSymbolAddress((void**)&x1,   g_x1);
    cudaGetSymbolAddress((void**)&x2,   g_x2);
    cudaGetSymbolAddress((void**)&t,    g_t);

    // Block 1: x1 = LN(inp + MHA1(inp))
    launch_mha(inp, w_qkv_1, mh1_W1, mh1_W2, c1_W1, c1_W2,
               qkv, hbuf, sq, bmat, att, z1, mout);
    add_ln_kernel<<<IN_, 256>>>(inp, mout, norm_w, norm_b, x1);

    // Block 2: x2 = LN(inp + MHA2(x1))   (note: residual is inp, per reference)
    launch_mha(x1, w_qkv_2, mh2_W1, mh2_W2, c2_W1, c2_W2,
               qkv, hbuf, sq, bmat, att, z1, mout);
    add_ln_kernel<<<IN_, 256>>>(inp, mout, norm_w, norm_b, x2);

    // Two FFN heads
    launch_ffn(x2, l1_W1, l1_W2, t, out);
    launch_ffn(x2, l2_W1, l2_W2, t, out + (long long)IN_ * SEQ_);
}

// round 5
// speedup vs baseline: 1.4945x; 1.4945x over previous
#include <cuda_runtime.h>
#include <cstdint>

// Problem dims
#define H_   8
#define IN_  512
#define SEQ_ 1024
#define MID_ 2048

constexpr int BM = 128, BN = 128, BK = 16;

// ---------------- scratch (device globals; no allocation allowed) ----------------
__device__ float g_qkv [3 * IN_ * SEQ_];          //  6 MB
__device__ float g_hbuf[H_ * 3 * IN_ * MID_];     // 96 MB
__device__ float g_sq  [H_ * 3 * IN_ * SEQ_];     // 48 MB
__device__ float g_bmat[H_ * SEQ_ * SEQ_];        // 32 MB
__device__ float g_att [H_ * IN_ * SEQ_];         // 16 MB
__device__ float g_z1  [MID_ * SEQ_];             //  8 MB
__device__ float g_mout[IN_ * SEQ_];
__device__ float g_x1  [IN_ * SEQ_];
__device__ float g_x2  [IN_ * SEQ_];
__device__ float g_t   [MID_ * SEQ_];             //  8 MB

// ---------------- tf32 helpers ----------------
__device__ __forceinline__ uint32_t f2tf32(float x) {
    uint32_t y;
    asm("cvt.rna.tf32.f32 %0, %1;" : "=r"(y) : "f"(x));
    return y;
}

__device__ __forceinline__ void mma_tf32(float c[4], const uint32_t a[4], const uint32_t b[2]) {
    asm volatile(
        "mma.sync.aligned.m16n8k8.row.col.f32.tf32.tf32.f32 "
        "{%0,%1,%2,%3}, {%4,%5,%6,%7}, {%8,%9}, {%0,%1,%2,%3};\n"
        : "+f"(c[0]), "+f"(c[1]), "+f"(c[2]), "+f"(c[3])
        : "r"(a[0]), "r"(a[1]), "r"(a[2]), "r"(a[3]), "r"(b[0]), "r"(b[1]));
}

// ---------------- generic batched GEMM: C = act( op(A) * op(B) [+ Res] ) ----------------
// A: !TA -> (M,K) row-major ; TA -> stored (K,M)
// B: !TB -> (K,N) row-major ; TB -> stored (N,K)
// C: (M,N) row-major. RA/RB: relu applied to A/B elements on load.
// RO: relu on output. RES: C += Res (Res same layout as C, no batch stride needed here).
// 3xTF32 split precision: fp32-quality results from tf32 tensor cores.
template<bool TA, bool TB, bool RA, bool RB, bool RO, bool RES>
__global__ void __launch_bounds__(256)
gemm_tf32(const float* __restrict__ A, const float* __restrict__ B,
          float* __restrict__ C, const float* __restrict__ Res,
          int M, int N, int K, long long sA, long long sB, long long sC)
{
    A += (long long)blockIdx.z * sA;
    B += (long long)blockIdx.z * sB;
    C += (long long)blockIdx.z * sC;

    const int bm = blockIdx.y * BM;
    const int bn = blockIdx.x * BN;

    __shared__ uint32_t AsHi[BK][BM + 1];
    __shared__ uint32_t AsLo[BK][BM + 1];
    __shared__ uint32_t BsHi[BK][BN + 1];
    __shared__ uint32_t BsLo[BK][BN + 1];

    const int tid  = threadIdx.x;
    const int lane = tid & 31;
    const int warp = tid >> 5;
    const int wm = (warp & 1) * 64;   // 2 warps along M
    const int wn = (warp >> 1) * 32;  // 4 warps along N
    const int ar = lane >> 2;         // mma group id
    const int ac = lane & 3;          // mma thread-in-group

    float acc[4][4][4];
#pragma unroll
    for (int i = 0; i < 4; ++i)
#pragma unroll
        for (int j = 0; j < 4; ++j)
#pragma unroll
            for (int r = 0; r < 4; ++r) acc[i][j][r] = 0.f;

    for (int k0 = 0; k0 < K; k0 += BK) {
        // ---- stage A tile (128 x 16) ----
#pragma unroll
        for (int it = 0; it < (BM * BK) / 256; ++it) {
            int idx = tid + it * 256;
            int mm, kk;
            long long gidx;
            if (!TA) { mm = idx >> 4;  kk = idx & 15;  gidx = (long long)(bm + mm) * K + (k0 + kk); }
            else     { kk = idx >> 7;  mm = idx & 127; gidx = (long long)(k0 + kk) * M + (bm + mm); }
            float v = A[gidx];
            if (RA) v = fmaxf(v, 0.f);
            uint32_t hi = f2tf32(v);
            AsHi[kk][mm] = hi;
            AsLo[kk][mm] = f2tf32(v - __uint_as_float(hi));
        }
        // ---- stage B tile (16 x 128) ----
#pragma unroll
        for (int it = 0; it < (BN * BK) / 256; ++it) {
            int idx = tid + it * 256;
            int nn, kk;
            long long gidx;
            if (!TB) { kk = idx >> 7;  nn = idx & 127; gidx = (long long)(k0 + kk) * N + (bn + nn); }
            else     { nn = idx >> 4;  kk = idx & 15;  gidx = (long long)(bn + nn) * K + (k0 + kk); }
            float v = B[gidx];
            if (RB) v = fmaxf(v, 0.f);
            uint32_t hi = f2tf32(v);
            BsHi[kk][nn] = hi;
            BsLo[kk][nn] = f2tf32(v - __uint_as_float(hi));
        }
        __syncthreads();

#pragma unroll
        for (int kk = 0; kk < BK; kk += 8) {
            uint32_t a[4][4], a2[4][4], b[4][2];
            // hi(A)
#pragma unroll
            for (int i = 0; i < 4; ++i) {
                int m0 = wm + i * 16 + ar;
                a[i][0] = AsHi[kk + ac][m0];
                a[i][1] = AsHi[kk + ac][m0 + 8];
                a[i][2] = AsHi[kk + ac + 4][m0];
                a[i][3] = AsHi[kk + ac + 4][m0 + 8];
            }
            // hi(B)
#pragma unroll
            for (int j = 0; j < 4; ++j) {
                int n0 = wn + j * 8 + ar;
                b[j][0] = BsHi[kk + ac][n0];
                b[j][1] = BsHi[kk + ac + 4][n0];
            }
            // hi*hi
#pragma unroll
            for (int i = 0; i < 4; ++i)
#pragma unroll
                for (int j = 0; j < 4; ++j) mma_tf32(acc[i][j], a[i], b[j]);
            // lo(A) * hi(B)
#pragma unroll
            for (int i = 0; i < 4; ++i) {
                int m0 = wm + i * 16 + ar;
                a2[i][0] = AsLo[kk + ac][m0];
                a2[i][1] = AsLo[kk + ac][m0 + 8];
                a2[i][2] = AsLo[kk + ac + 4][m0];
                a2[i][3] = AsLo[kk + ac + 4][m0 + 8];
            }
#pragma unroll
            for (int i = 0; i < 4; ++i)
#pragma unroll
                for (int j = 0; j < 4; ++j) mma_tf32(acc[i][j], a2[i], b[j]);
            // hi(A) * lo(B)
#pragma unroll
            for (int j = 0; j < 4; ++j) {
                int n0 = wn + j * 8 + ar;
                b[j][0] = BsLo[kk + ac][n0];
                b[j][1] = BsLo[kk + ac + 4][n0];
            }
#pragma unroll
            for (int i = 0; i < 4; ++i)
#pragma unroll
                for (int j = 0; j < 4; ++j) mma_tf32(acc[i][j], a[i], b[j]);
        }
        __syncthreads();
    }

    // ---- epilogue ----
#pragma unroll
    for (int i = 0; i < 4; ++i) {
        int m0 = bm + wm + i * 16 + ar;
#pragma unroll
        for (int j = 0; j < 4; ++j) {
            int n0 = bn + wn + j * 8 + ac * 2;
            long long o0 = (long long)m0 * N + n0;
            long long o1 = o0 + 8LL * N;
            float v0 = acc[i][j][0], v1 = acc[i][j][1];
            float v2 = acc[i][j][2], v3 = acc[i][j][3];
            if (RES) {
                v0 += Res[o0]; v1 += Res[o0 + 1];
                v2 += Res[o1]; v3 += Res[o1 + 1];
            }
            if (RO) {
                v0 = fmaxf(v0, 0.f); v1 = fmaxf(v1, 0.f);
                v2 = fmaxf(v2, 0.f); v3 = fmaxf(v3, 0.f);
            }
            C[o0] = v0; C[o0 + 1] = v1;
            C[o1] = v2; C[o1 + 1] = v3;
        }
    }
}

// ---------------- fused residual add + layernorm over last axis (1024) ----------------
__global__ void add_ln_kernel(const float* __restrict__ a, const float* __restrict__ b,
                              const float* __restrict__ w, const float* __restrict__ bias,
                              float* __restrict__ out)
{
    const int row = blockIdx.x;
    const int tid = threadIdx.x;
    const long long base = (long long)row * SEQ_;
    float v[4];
    float s = 0.f, ss = 0.f;
#pragma unroll
    for (int i = 0; i < 4; ++i) {
        int col = tid + i * 256;
        float t = a[base + col] + b[base + col];
        v[i] = t; s += t; ss += t * t;
    }
#pragma unroll
    for (int o = 16; o > 0; o >>= 1) {
        s  += __shfl_xor_sync(0xffffffffu, s,  o);
        ss += __shfl_xor_sync(0xffffffffu, ss, o);
    }
    __shared__ float rs[8], rss[8];
    if ((tid & 31) == 0) { rs[tid >> 5] = s; rss[tid >> 5] = ss; }
    __syncthreads();
    s = 0.f; ss = 0.f;
#pragma unroll
    for (int i = 0; i < 8; ++i) { s += rs[i]; ss += rss[i]; }
    const float mu  = s  * (1.0f / SEQ_);
    const float var = ss * (1.0f / SEQ_) - mu * mu;
    const float inv = rsqrtf(var + 1e-6f);
#pragma unroll
    for (int i = 0; i < 4; ++i) {
        int col = tid + i * 256;
        out[base + col] = (v[i] - mu) * inv * w[col] + bias[col];
    }
}

// ---------------- host orchestration ----------------
static void launch_mha(const float* x, const float* wqkv, const float* W1, const float* W2,
                       const float* cW1, const float* cW2,
                       float* qkv, float* hbuf, float* sq, float* bmat, float* att,
                       float* z1, float* mout)
{
    // 1. qkv[c] = w_qkv[c] @ x                     (512,1024,K=512) x3
    gemm_tf32<false,false,false,false,false,false><<<dim3(SEQ_/BN, IN_/BM, 3), 256>>>(
        wqkv, x, qkv, nullptr, IN_, SEQ_, IN_,
        (long long)IN_*IN_, 0, (long long)IN_*SEQ_);
    // 2. h[h,c] = relu( relu(qkv[c]) @ W1[h,c]^T ) (512,2048,K=1024) x24
    for (int c = 0; c < 3; ++c)
        gemm_tf32<false,true,true,false,true,false><<<dim3(MID_/BN, IN_/BM, H_), 256>>>(
            qkv + (long long)c*IN_*SEQ_, W1 + (long long)c*MID_*SEQ_,
            hbuf + (long long)c*IN_*MID_, nullptr,
            IN_, MID_, SEQ_,
            0, (long long)3*MID_*SEQ_, (long long)3*IN_*MID_);
    // 3. sq[h,c] = h[h,c] @ W2[h,c]^T              (512,1024,K=2048) x24
    for (int c = 0; c < 3; ++c)
        gemm_tf32<false,true,false,false,false,false><<<dim3(SEQ_/BN, IN_/BM, H_), 256>>>(
            hbuf + (long long)c*IN_*MID_, W2 + (long long)c*SEQ_*MID_,
            sq + (long long)c*IN_*SEQ_, nullptr,
            IN_, SEQ_, MID_,
            (long long)3*IN_*MID_, (long long)3*SEQ_*MID_, (long long)3*IN_*SEQ_);
    // 4. b[h] = k[h]^T @ q[h]                      (1024,1024,K=512) x8  (TN)
    gemm_tf32<true,false,false,false,false,false><<<dim3(SEQ_/BN, SEQ_/BM, H_), 256>>>(
        sq + (long long)IN_*SEQ_, sq, bmat, nullptr,
        SEQ_, SEQ_, IN_,
        (long long)3*IN_*SEQ_, (long long)3*IN_*SEQ_, (long long)SEQ_*SEQ_);
    // 5. att[h] = v[h] @ b[h]                      (512,1024,K=1024) x8
    gemm_tf32<false,false,false,false,false,false><<<dim3(SEQ_/BN, IN_/BM, H_), 256>>>(
        sq + (long long)2*IN_*SEQ_, bmat, att, nullptr,
        IN_, SEQ_, SEQ_,
        (long long)3*IN_*SEQ_, (long long)SEQ_*SEQ_, (long long)IN_*SEQ_);
    // 6. z1t = relu( cW1 @ relu(att_flat) )        (2048,1024,K=4096)
    gemm_tf32<false,false,false,true,true,false><<<dim3(SEQ_/BN, MID_/BM, 1), 256>>>(
        cW1, att, z1, nullptr, MID_, SEQ_, H_*IN_, 0, 0, 0);
    // 7. mout = cW2 @ relu(z1t)                    (512,1024,K=2048)
    gemm_tf32<false,false,false,true,false,false><<<dim3(SEQ_/BN, IN_/BM, 1), 256>>>(
        cW2, z1, mout, nullptr, IN_, SEQ_, MID_, 0, 0, 0);
}

static void launch_ffn(const float* x2, const float* Wa, const float* Wb,
                       float* t, float* out)
{
    // t = relu( Wa @ relu(x2) )                    (2048,1024,K=512)
    gemm_tf32<false,false,false,true,true,false><<<dim3(SEQ_/BN, MID_/BM, 1), 256>>>(
        Wa, x2, t, nullptr, MID_, SEQ_, IN_, 0, 0, 0);
    // out = Wb @ relu(t) + x2                      (512,1024,K=2048)
    gemm_tf32<false,false,false,true,false,true><<<dim3(SEQ_/BN, IN_/BM, 1), 256>>>(
        Wb, t, out, x2, IN_, SEQ_, MID_, 0, 0, 0);
}

extern "C" void kernel_launch(void* const* d_in, const int* in_sizes, int n_in,
                              void* d_out, int out_size)
{
    (void)in_sizes; (void)n_in; (void)out_size;

    const float* inp     = (const float*)d_in[0];
    const float* w_qkv_1 = (const float*)d_in[1];
    const float* w_qkv_2 = (const float*)d_in[2];
    const float* mh1_W1  = (const float*)d_in[3];
    const float* mh1_W2  = (const float*)d_in[4];
    const float* mh2_W1  = (const float*)d_in[5];
    const float* mh2_W2  = (const float*)d_in[6];
    const float* c1_W1   = (const float*)d_in[7];
    const float* c1_W2   = (const float*)d_in[8];
    const float* c2_W1   = (const float*)d_in[9];
    const float* c2_W2   = (const float*)d_in[10];
    const float* l1_W1   = (const float*)d_in[11];
    const float* l1_W2   = (const float*)d_in[12];
    const float* l2_W1   = (const float*)d_in[13];
    const float* l2_W2   = (const float*)d_in[14];
    const float* norm_w  = (const float*)d_in[15];
    const float* norm_b  = (const float*)d_in[16];
    float* out = (float*)d_out;

    float *qkv, *hbuf, *sq, *bmat, *att, *z1, *mout, *x1, *x2, *t;
    cudaGetSymbolAddress((void**)&qkv,  g_qkv);
    cudaGetSymbolAddress((void**)&hbuf, g_hbuf);
    cudaGetSymbolAddress((void**)&sq,   g_sq);
    cudaGetSymbolAddress((void**)&bmat, g_bmat);
    cudaGetSymbolAddress((void**)&att,  g_att);
    cudaGetSymbolAddress((void**)&z1,   g_z1);
    cudaGetSymbolAddress((void**)&mout, g_mout);
    cudaGetSymbolAddress((void**)&x1,   g_x1);
    cudaGetSymbolAddress((void**)&x2,   g_x2);
    cudaGetSymbolAddress((void**)&t,    g_t);

    // Block 1: x1 = LN(inp + MHA1(inp))
    launch_mha(inp, w_qkv_1, mh1_W1, mh1_W2, c1_W1, c1_W2,
               qkv, hbuf, sq, bmat, att, z1, mout);
    add_ln_kernel<<<IN_, 256>>>(inp, mout, norm_w, norm_b, x1);

    // Block 2: x2 = LN(inp + MHA2(x1))   (note: residual is inp, per reference)
    launch_mha(x1, w_qkv_2, mh2_W1, mh2_W2, c2_W1, c2_W2,
               qkv, hbuf, sq, bmat, att, z1, mout);
    add_ln_kernel<<<IN_, 256>>>(inp, mout, norm_w, norm_b, x2);

    // Two FFN heads
    launch_ffn(x2, l1_W1, l1_W2, t, out);
    launch_ffn(x2, l2_W1, l2_W2, t, out + (long long)IN_ * SEQ_);
}

// round 6
// speedup vs baseline: 1.4950x; 1.0004x over previous
#include <cuda_runtime.h>
#include <cstdint>

// Problem dims
#define H_   8
#define IN_  512
#define SEQ_ 1024
#define MID_ 2048

constexpr int BM = 128, BN = 128, BK = 16;

// ---------------- scratch (device globals; no allocation allowed) ----------------
__device__ float g_qkv [3 * IN_ * SEQ_];          //  6 MB
__device__ float g_hbuf[H_ * 3 * IN_ * MID_];     // 96 MB
__device__ float g_sq  [H_ * 3 * IN_ * SEQ_];     // 48 MB
__device__ float g_bmat[H_ * SEQ_ * SEQ_];        // 32 MB
__device__ float g_att [H_ * IN_ * SEQ_];         // 16 MB
__device__ float g_z1  [MID_ * SEQ_];             //  8 MB
__device__ float g_mout[IN_ * SEQ_];
__device__ float g_x1  [IN_ * SEQ_];
__device__ float g_x2  [IN_ * SEQ_];
__device__ float g_t   [MID_ * SEQ_];             //  8 MB

// ---------------- tf32 helpers ----------------
__device__ __forceinline__ uint32_t f2tf32(float x) {
    uint32_t y;
    asm("cvt.rna.tf32.f32 %0, %1;" : "=r"(y) : "f"(x));
    return y;
}

__device__ __forceinline__ void mma_tf32(float c[4], const uint32_t a[4], const uint32_t b[2]) {
    asm volatile(
        "mma.sync.aligned.m16n8k8.row.col.f32.tf32.tf32.f32 "
        "{%0,%1,%2,%3}, {%4,%5,%6,%7}, {%8,%9}, {%0,%1,%2,%3};\n"
        : "+f"(c[0]), "+f"(c[1]), "+f"(c[2]), "+f"(c[3])
        : "r"(a[0]), "r"(a[1]), "r"(a[2]), "r"(a[3]), "r"(b[0]), "r"(b[1]));
}

// ---------------- generic batched GEMM: C = act( op(A) * op(B) [+ Res] ) ----------------
// A: !TA -> (M,K) row-major ; TA -> stored (K,M)
// B: !TB -> (K,N) row-major ; TB -> stored (N,K)
// C: (M,N) row-major. RA/RB: relu applied to A/B elements on load.
// RO: relu on output. RES: C += Res (Res same layout as C, no batch stride needed here).
// 3xTF32 split precision: fp32-quality results from tf32 tensor cores.
template<bool TA, bool TB, bool RA, bool RB, bool RO, bool RES>
__global__ void __launch_bounds__(256)
gemm_tf32(const float* __restrict__ A, const float* __restrict__ B,
          float* __restrict__ C, const float* __restrict__ Res,
          int M, int N, int K, long long sA, long long sB, long long sC)
{
    A += (long long)blockIdx.z * sA;
    B += (long long)blockIdx.z * sB;
    C += (long long)blockIdx.z * sC;

    const int bm = blockIdx.y * BM;
    const int bn = blockIdx.x * BN;

    __shared__ uint32_t AsHi[BK][BM + 1];
    __shared__ uint32_t AsLo[BK][BM + 1];
    __shared__ uint32_t BsHi[BK][BN + 1];
    __shared__ uint32_t BsLo[BK][BN + 1];

    const int tid  = threadIdx.x;
    const int lane = tid & 31;
    const int warp = tid >> 5;
    const int wm = (warp & 1) * 64;   // 2 warps along M
    const int wn = (warp >> 1) * 32;  // 4 warps along N
    const int ar = lane >> 2;         // mma group id
    const int ac = lane & 3;          // mma thread-in-group

    float acc[4][4][4];
#pragma unroll
    for (int i = 0; i < 4; ++i)
#pragma unroll
        for (int j = 0; j < 4; ++j)
#pragma unroll
            for (int r = 0; r < 4; ++r) acc[i][j][r] = 0.f;

    for (int k0 = 0; k0 < K; k0 += BK) {
        // ---- stage A tile (128 x 16) ----
#pragma unroll
        for (int it = 0; it < (BM * BK) / 256; ++it) {
            int idx = tid + it * 256;
            int mm, kk;
            long long gidx;
            if (!TA) { mm = idx >> 4;  kk = idx & 15;  gidx = (long long)(bm + mm) * K + (k0 + kk); }
            else     { kk = idx >> 7;  mm = idx & 127; gidx = (long long)(k0 + kk) * M + (bm + mm); }
            float v = A[gidx];
            if (RA) v = fmaxf(v, 0.f);
            uint32_t hi = f2tf32(v);
            AsHi[kk][mm] = hi;
            AsLo[kk][mm] = f2tf32(v - __uint_as_float(hi));
        }
        // ---- stage B tile (16 x 128) ----
#pragma unroll
        for (int it = 0; it < (BN * BK) / 256; ++it) {
            int idx = tid + it * 256;
            int nn, kk;
            long long gidx;
            if (!TB) { kk = idx >> 7;  nn = idx & 127; gidx = (long long)(k0 + kk) * N + (bn + nn); }
            else     { nn = idx >> 4;  kk = idx & 15;  gidx = (long long)(bn + nn) * K + (k0 + kk); }
            float v = B[gidx];
            if (RB) v = fmaxf(v, 0.f);
            uint32_t hi = f2tf32(v);
            BsHi[kk][nn] = hi;
            BsLo[kk][nn] = f2tf32(v - __uint_as_float(hi));
        }
        __syncthreads();

#pragma unroll
        for (int kk = 0; kk < BK; kk += 8) {
            uint32_t a[4][4], a2[4][4], b[4][2];
            // hi(A)
#pragma unroll
            for (int i = 0; i < 4; ++i) {
                int m0 = wm + i * 16 + ar;
                a[i][0] = AsHi[kk + ac][m0];
                a[i][1] = AsHi[kk + ac][m0 + 8];
                a[i][2] = AsHi[kk + ac + 4][m0];
                a[i][3] = AsHi[kk + ac + 4][m0 + 8];
            }
            // hi(B)
#pragma unroll
            for (int j = 0; j < 4; ++j) {
                int n0 = wn + j * 8 + ar;
                b[j][0] = BsHi[kk + ac][n0];
                b[j][1] = BsHi[kk + ac + 4][n0];
            }
            // hi*hi
#pragma unroll
            for (int i = 0; i < 4; ++i)
#pragma unroll
                for (int j = 0; j < 4; ++j) mma_tf32(acc[i][j], a[i], b[j]);
            // lo(A) * hi(B)
#pragma unroll
            for (int i = 0; i < 4; ++i) {
                int m0 = wm + i * 16 + ar;
                a2[i][0] = AsLo[kk + ac][m0];
                a2[i][1] = AsLo[kk + ac][m0 + 8];
                a2[i][2] = AsLo[kk + ac + 4][m0];
                a2[i][3] = AsLo[kk + ac + 4][m0 + 8];
            }
#pragma unroll
            for (int i = 0; i < 4; ++i)
#pragma unroll
                for (int j = 0; j < 4; ++j) mma_tf32(acc[i][j], a2[i], b[j]);
            // hi(A) * lo(B)
#pragma unroll
            for (int j = 0; j < 4; ++j) {
                int n0 = wn + j * 8 + ar;
                b[j][0] = BsLo[kk + ac][n0];
                b[j][1] = BsLo[kk + ac + 4][n0];
            }
#pragma unroll
            for (int i = 0; i < 4; ++i)
#pragma unroll
                for (int j = 0; j < 4; ++j) mma_tf32(acc[i][j], a[i], b[j]);
        }
        __syncthreads();
    }

    // ---- epilogue ----
#pragma unroll
    for (int i = 0; i < 4; ++i) {
        int m0 = bm + wm + i * 16 + ar;
#pragma unroll
        for (int j = 0; j < 4; ++j) {
            int n0 = bn + wn + j * 8 + ac * 2;
            long long o0 = (long long)m0 * N + n0;
            long long o1 = o0 + 8LL * N;
            float v0 = acc[i][j][0], v1 = acc[i][j][1];
            float v2 = acc[i][j][2], v3 = acc[i][j][3];
            if (RES) {
                v0 += Res[o0]; v1 += Res[o0 + 1];
                v2 += Res[o1]; v3 += Res[o1 + 1];
            }
            if (RO) {
                v0 = fmaxf(v0, 0.f); v1 = fmaxf(v1, 0.f);
                v2 = fmaxf(v2, 0.f); v3 = fmaxf(v3, 0.f);
            }
            C[o0] = v0; C[o0 + 1] = v1;
            C[o1] = v2; C[o1 + 1] = v3;
        }
    }
}

// ---------------- fused residual add + layernorm over last axis (1024) ----------------
__global__ void add_ln_kernel(const float* __restrict__ a, const float* __restrict__ b,
                              const float* __restrict__ w, const float* __restrict__ bias,
                              float* __restrict__ out)
{
    const int row = blockIdx.x;
    const int tid = threadIdx.x;
    const long long base = (long long)row * SEQ_;
    float v[4];
    float s = 0.f, ss = 0.f;
#pragma unroll
    for (int i = 0; i < 4; ++i) {
        int col = tid + i * 256;
        float t = a[base + col] + b[base + col];
        v[i] = t; s += t; ss += t * t;
    }
#pragma unroll
    for (int o = 16; o > 0; o >>= 1) {
        s  += __shfl_xor_sync(0xffffffffu, s,  o);
        ss += __shfl_xor_sync(0xffffffffu, ss, o);
    }
    __shared__ float rs[8], rss[8];
    if ((tid & 31) == 0) { rs[tid >> 5] = s; rss[tid >> 5] = ss; }
    __syncthreads();
    s = 0.f; ss = 0.f;
#pragma unroll
    for (int i = 0; i < 8; ++i) { s += rs[i]; ss += rss[i]; }
    const float mu  = s  * (1.0f / SEQ_);
    const float var = ss * (1.0f / SEQ_) - mu * mu;
    const float inv = rsqrtf(var + 1e-6f);
#pragma unroll
    for (int i = 0; i < 4; ++i) {
        int col = tid + i * 256;
        out[base + col] = (v[i] - mu) * inv * w[col] + bias[col];
    }
}

// ---------------- host orchestration ----------------
static void launch_mha(const float* x, const float* wqkv, const float* W1, const float* W2,
                       const float* cW1, const float* cW2,
                       float* qkv, float* hbuf, float* sq, float* bmat, float* att,
                       float* z1, float* mout)
{
    // 1. qkv[c] = w_qkv[c] @ x                     (512,1024,K=512) x3
    gemm_tf32<false,false,false,false,false,false><<<dim3(SEQ_/BN, IN_/BM, 3), 256>>>(
        wqkv, x, qkv, nullptr, IN_, SEQ_, IN_,
        (long long)IN_*IN_, 0, (long long)IN_*SEQ_);
    // 2. h[h,c] = relu( relu(qkv[c]) @ W1[h,c]^T ) (512,2048,K=1024) x24
    for (int c = 0; c < 3; ++c)
        gemm_tf32<false,true,true,false,true,false><<<dim3(MID_/BN, IN_/BM, H_), 256>>>(
            qkv + (long long)c*IN_*SEQ_, W1 + (long long)c*MID_*SEQ_,
            hbuf + (long long)c*IN_*MID_, nullptr,
            IN_, MID_, SEQ_,
            0, (long long)3*MID_*SEQ_, (long long)3*IN_*MID_);
    // 3. sq[h,c] = h[h,c] @ W2[h,c]^T              (512,1024,K=2048) x24
    for (int c = 0; c < 3; ++c)
        gemm_tf32<false,true,false,false,false,false><<<dim3(SEQ_/BN, IN_/BM, H_), 256>>>(
            hbuf + (long long)c*IN_*MID_, W2 + (long long)c*SEQ_*MID_,
            sq + (long long)c*IN_*SEQ_, nullptr,
            IN_, SEQ_, MID_,
            (long long)3*IN_*MID_, (long long)3*SEQ_*MID_, (long long)3*IN_*SEQ_);
    // 4. b[h] = k[h]^T @ q[h]                      (1024,1024,K=512) x8  (TN)
    gemm_tf32<true,false,false,false,false,false><<<dim3(SEQ_/BN, SEQ_/BM, H_), 256>>>(
        sq + (long long)IN_*SEQ_, sq, bmat, nullptr,
        SEQ_, SEQ_, IN_,
        (long long)3*IN_*SEQ_, (long long)3*IN_*SEQ_, (long long)SEQ_*SEQ_);
    // 5. att[h] = v[h] @ b[h]                      (512,1024,K=1024) x8
    gemm_tf32<false,false,false,false,false,false><<<dim3(SEQ_/BN, IN_/BM, H_), 256>>>(
        sq + (long long)2*IN_*SEQ_, bmat, att, nullptr,
        IN_, SEQ_, SEQ_,
        (long long)3*IN_*SEQ_, (long long)SEQ_*SEQ_, (long long)IN_*SEQ_);
    // 6. z1t = relu( cW1 @ relu(att_flat) )        (2048,1024,K=4096)
    gemm_tf32<false,false,false,true,true,false><<<dim3(SEQ_/BN, MID_/BM, 1), 256>>>(
        cW1, att, z1, nullptr, MID_, SEQ_, H_*IN_, 0, 0, 0);
    // 7. mout = cW2 @ relu(z1t)                    (512,1024,K=2048)
    gemm_tf32<false,false,false,true,false,false><<<dim3(SEQ_/BN, IN_/BM, 1), 256>>>(
        cW2, z1, mout, nullptr, IN_, SEQ_, MID_, 0, 0, 0);
}

static void launch_ffn(const float* x2, const float* Wa, const float* Wb,
                       float* t, float* out)
{
    // t = relu( Wa @ relu(x2) )                    (2048,1024,K=512)
    gemm_tf32<false,false,false,true,true,false><<<dim3(SEQ_/BN, MID_/BM, 1), 256>>>(
        Wa, x2, t, nullptr, MID_, SEQ_, IN_, 0, 0, 0);
    // out = Wb @ relu(t) + x2                      (512,1024,K=2048)
    gemm_tf32<false,false,false,true,false,true><<<dim3(SEQ_/BN, IN_/BM, 1), 256>>>(
        Wb, t, out, x2, IN_, SEQ_, MID_, 0, 0, 0);
}

extern "C" void kernel_launch(void* const* d_in, const int* in_sizes, int n_in,
                              void* d_out, int out_size)
{
    (void)in_sizes; (void)n_in; (void)out_size;

    const float* inp     = (const float*)d_in[0];
    const float* w_qkv_1 = (const float*)d_in[1];
    const float* w_qkv_2 = (const float*)d_in[2];
    const float* mh1_W1  = (const float*)d_in[3];
    const float* mh1_W2  = (const float*)d_in[4];
    const float* mh2_W1  = (const float*)d_in[5];
    const float* mh2_W2  = (const float*)d_in[6];
    const float* c1_W1   = (const float*)d_in[7];
    const float* c1_W2   = (const float*)d_in[8];
    const float* c2_W1   = (const float*)d_in[9];
    const float* c2_W2   = (const float*)d_in[10];
    const float* l1_W1   = (const float*)d_in[11];
    const float* l1_W2   = (const float*)d_in[12];
    const float* l2_W1   = (const float*)d_in[13];
    const float* l2_W2   = (const float*)d_in[14];
    const float* norm_w  = (const float*)d_in[15];
    const float* norm_b  = (const float*)d_in[16];
    float* out = (float*)d_out;

    float *qkv, *hbuf, *sq, *bmat, *att, *z1, *mout, *x1, *x2, *t;
    cudaGetSymbolAddress((void**)&qkv,  g_qkv);
    cudaGetSymbolAddress((void**)&hbuf, g_hbuf);
    cudaGetSymbolAddress((void**)&sq,   g_sq);
    cudaGetSymbolAddress((void**)&bmat, g_bmat);
    cudaGetSymbolAddress((void**)&att,  g_att);
    cudaGetSymbolAddress((void**)&z1,   g_z1);
    cudaGetSymbolAddress((void**)&mout, g_mout);
    cudaGetSymbolAddress((void**)&x1,   g_x1);
    cudaGetSymbolAddress((void**)&x2,   g_x2);
    cudaGetSymbolAddress((void**)&t,    g_t);

    // Block 1: x1 = LN(inp + MHA1(inp))
    launch_mha(inp, w_qkv_1, mh1_W1, mh1_W2, c1_W1, c1_W2,
               qkv, hbuf, sq, bmat, att, z1, mout);
    add_ln_kernel<<<IN_, 256>>>(inp, mout, norm_w, norm_b, x1);

    // Block 2: x2 = LN(inp + MHA2(x1))   (note: residual is inp, per reference)
    launch_mha(x1, w_qkv_2, mh2_W1, mh2_W2, c2_W1, c2_W2,
               qkv, hbuf, sq, bmat, att, z1, mout);
    add_ln_kernel<<<IN_, 256>>>(inp, mout, norm_w, norm_b, x2);

    // Two FFN heads
    launch_ffn(x2, l1_W1, l1_W2, t, out);
    launch_ffn(x2, l2_W1, l2_W2, t, out + (long long)IN_ * SEQ_);
}